// round 17
// baseline (speedup 1.0000x reference)
#include <cuda_runtime.h>
#include <cuda_fp16.h>
#include <cstdint>

// Problem constants (fixed by the dataset)
#define T_TOK   16384
#define D_DIM   4096
#define E_EXP   64
#define BM      128             // tokens per block
#define BK      64              // fp32 k per chunk (4 k16 steps, kh-split over warp halves)
#define NCHUNK  (D_DIM / BK)    // 64
#define NBLK    (T_TOK / BM)    // 128
#define NT      512             // 16 warps: 4/SMSP, 2 per phase role
#define NSTAGE  4

// fp16 plane tiles, row stride 144 B (128B data + 16B pad -> LDSM conflict-free)
#define RSB       144
#define AH_O      0
#define AL_O      18432          // 128 rows * 144
#define BH_O      36864
#define BL_O      46080          // + 64 * 144
#define STAGE_SZ  55296
#define SMEM_BYTES (NSTAGE * STAGE_SZ)   // 221184; Ls[128][65]=33280 overlays stage0

static __device__ float g_ssum[NBLK * E_EXP];
static __device__ int   g_cnt [NBLK * E_EXP];
static __device__ int   g_arrived;   // zero-init; reset by last block each launch

// ---------- helpers ----------
__device__ __forceinline__ uint32_t smem_u32(const void* p) {
    uint32_t a;
    asm("{ .reg .u64 t; cvta.to.shared.u64 t, %1; cvt.u32.u64 %0, t; }" : "=r"(a) : "l"(p));
    return a;
}
__device__ __forceinline__ void cvt_split2(float x0, float x1, uint32_t& h, uint32_t& lo) {
    __half2 hh = __floats2half2_rn(x0, x1);          // low = x0, high = x1
    h = *reinterpret_cast<uint32_t*>(&hh);
    float2 hf = __half22float2(hh);
    __half2 ll = __floats2half2_rn(x0 - hf.x, x1 - hf.y);
    lo = *reinterpret_cast<uint32_t*>(&ll);
}
__device__ __forceinline__ void st2u(uint32_t a, uint32_t x, uint32_t y) {
    asm volatile("st.shared.v2.u32 [%0], {%1,%2};" :: "r"(a), "r"(x), "r"(y));
}
__device__ __forceinline__ void ldsm4(uint32_t a, uint32_t* r) {
    asm volatile("ldmatrix.sync.aligned.m8n8.x4.shared.b16 {%0,%1,%2,%3}, [%4];"
                 : "=r"(r[0]), "=r"(r[1]), "=r"(r[2]), "=r"(r[3]) : "r"(a));
}
__device__ __forceinline__ void mma_f16(float* d, const uint32_t* a, const uint32_t* b) {
    asm volatile(
        "mma.sync.aligned.m16n8k16.row.col.f32.f16.f16.f32 "
        "{%0,%1,%2,%3}, {%4,%5,%6,%7}, {%8,%9}, {%0,%1,%2,%3};"
        : "+f"(d[0]), "+f"(d[1]), "+f"(d[2]), "+f"(d[3])
        : "r"(a[0]), "r"(a[1]), "r"(a[2]), "r"(a[3]), "r"(b[0]), "r"(b[1]));
}

// ---------- single fused kernel ----------
__global__ void __launch_bounds__(NT, 1)
gate_main(const float* __restrict__ inp, const float* __restrict__ W,
          const float* __restrict__ bias, float* __restrict__ out)
{
    extern __shared__ char dsm[];
    __shared__ float s_inv[BM];
    __shared__ float s_ps[NT];
    __shared__ float s_b[E_EXP];
    __shared__ int   s_cnt[E_EXP];
    __shared__ int   s_last;
    __shared__ float rs2[NT];
    __shared__ int   rc2[NT];

    const uint32_t sb = smem_u32(dsm);
    const int tid = threadIdx.x;
    const int blk = blockIdx.x;
    const int w   = tid >> 5;
    const int l   = tid & 31;
    const int l4  = l >> 2;
    const int lk  = l & 3;
    // anti-phase: SMSP = w&3 hosts warps {w, w+4, w+8, w+12} -> kh = {0,0,1,1}
    const int kh  = (w >> 3) & 1;   // k16-step pair split AND phase role
    const int tg  = (w >> 1) & 3;   // 4 token groups of 32
    const int eg  = w & 1;          // 2 expert groups of 32

    if (tid < E_EXP) { s_b[tid] = bias[tid]; s_cnt[tid] = 0; }

    // ---- staging: A 2048 f4/chunk / 512 thr = 4 ; W 1024/512 = 2 ----
    const float4* baseA = (const float4*)(inp + (size_t)blk * BM * D_DIM);
    const float4* baseW = (const float4*)W;
    int offA[4]; uint32_t stA[4];
#pragma unroll
    for (int p = 0; p < 4; ++p) {
        int fid = p * NT + tid, row = fid >> 4, q4 = fid & 15;
        offA[p] = row * (D_DIM / 4) + q4;
        stA[p]  = (uint32_t)(row * RSB + q4 * 8);
    }
    int offW[2]; uint32_t stW[2];
#pragma unroll
    for (int p = 0; p < 2; ++p) {
        int fid = p * NT + tid, row = fid >> 4, q4 = fid & 15;
        offW[p] = row * (D_DIM / 4) + q4;
        stW[p]  = (uint32_t)(BH_O + row * RSB + q4 * 8);
    }

    // ---- ldmatrix per-lane base addresses ----
    uint32_t aLd[2];
#pragma unroll
    for (int i = 0; i < 2; ++i)
        aLd[i] = (uint32_t)((tg * 32 + i * 16 + ((l >> 3) & 1) * 8 + (l & 7)) * RSB
                            + (l >> 4) * 16);
    uint32_t bLd[2];
#pragma unroll
    for (int jp = 0; jp < 2; ++jp)
        bLd[jp] = (uint32_t)(BH_O + (eg * 32 + jp * 16 + (l >> 4) * 8 + (l & 7)) * RSB
                             + ((l >> 3) & 1) * 16);

    float acc[2][4][4];
#pragma unroll
    for (int i = 0; i < 2; ++i)
#pragma unroll
        for (int j = 0; j < 4; ++j)
#pragma unroll
            for (int r = 0; r < 4; ++r) acc[i][j][r] = 0.f;

    float4 ra[4], rw[2];

    #define LDG_CHUNK(cc)                                              \
        _Pragma("unroll")                                              \
        for (int p = 0; p < 4; ++p) ra[p] = baseA[offA[p] + (cc) * (BK / 4)]; \
        _Pragma("unroll")                                              \
        for (int p = 0; p < 2; ++p) rw[p] = baseW[offW[p] + (cc) * (BK / 4)];

    #define STS_CHUNK(tb)                                              \
        _Pragma("unroll")                                              \
        for (int p = 0; p < 4; ++p) {                                  \
            uint32_t h01, l01, h23, l23;                               \
            cvt_split2(ra[p].x, ra[p].y, h01, l01);                    \
            cvt_split2(ra[p].z, ra[p].w, h23, l23);                    \
            st2u((tb) + stA[p],        h01, h23);                      \
            st2u((tb) + stA[p] + AL_O, l01, l23);                      \
        }                                                              \
        _Pragma("unroll")                                              \
        for (int p = 0; p < 2; ++p) {                                  \
            uint32_t h01, l01, h23, l23;                               \
            cvt_split2(rw[p].x, rw[p].y, h01, l01);                    \
            cvt_split2(rw[p].z, rw[p].w, h23, l23);                    \
            st2u((tb) + stW[p],                 h01, h23);             \
            st2u((tb) + stW[p] + (BL_O - BH_O), l01, l23);             \
        }

    #define COMPUTE_CHUNK(tb)                                                      \
        _Pragma("unroll")                                                          \
        for (int ks2 = 0; ks2 < 2; ++ks2) {                                        \
            const uint32_t ko = (uint32_t)((kh * 2 + ks2) * 32);                   \
            uint32_t aH[2][4], aL[2][4], bHf[4][2], bLf[4][2];                     \
            _Pragma("unroll")                                                      \
            for (int i = 0; i < 2; ++i) ldsm4((tb) + aLd[i] + ko, aH[i]);          \
            _Pragma("unroll")                                                      \
            for (int jp = 0; jp < 2; ++jp) {                                       \
                uint32_t r[4];                                                     \
                ldsm4((tb) + bLd[jp] + ko, r);                                     \
                bHf[jp * 2][0] = r[0]; bHf[jp * 2][1] = r[1];                      \
                bHf[jp * 2 + 1][0] = r[2]; bHf[jp * 2 + 1][1] = r[3];              \
            }                                                                      \
            _Pragma("unroll")                                                      \
            for (int jp = 0; jp < 2; ++jp) {                                       \
                uint32_t r[4];                                                     \
                ldsm4((tb) + bLd[jp] + ko + (BL_O - BH_O), r);                     \
                bLf[jp * 2][0] = r[0]; bLf[jp * 2][1] = r[1];                      \
                bLf[jp * 2 + 1][0] = r[2]; bLf[jp * 2 + 1][1] = r[3];              \
            }                                                                      \
            _Pragma("unroll")                                                      \
            for (int i = 0; i < 2; ++i) ldsm4((tb) + aLd[i] + ko + AL_O, aL[i]);   \
            _Pragma("unroll")                                                      \
            for (int i = 0; i < 2; ++i)                                            \
                _Pragma("unroll")                                                  \
                for (int j = 0; j < 4; ++j)                                        \
                    mma_f16(acc[i][j], aH[i], bHf[j]);                             \
            _Pragma("unroll")                                                      \
            for (int i = 0; i < 2; ++i)                                            \
                _Pragma("unroll")                                                  \
                for (int j = 0; j < 4; ++j)                                        \
                    mma_f16(acc[i][j], aH[i], bLf[j]);                             \
            _Pragma("unroll")                                                      \
            for (int i = 0; i < 2; ++i)                                            \
                _Pragma("unroll")                                                  \
                for (int j = 0; j < 4; ++j)                                        \
                    mma_f16(acc[i][j], aL[i], bHf[j]);                             \
        }

    // ---- ramp: stage chunks 0,1 ; prefetch chunk 2 into regs ----
    LDG_CHUNK(0);
    STS_CHUNK(sb + 0 * STAGE_SZ);
    LDG_CHUNK(1);
    STS_CHUNK(sb + 1 * STAGE_SZ);
    LDG_CHUNK(2);
    __syncthreads();

    // 4-stage ring, producer distance 2, barrier every 2 chunks.
    // Hazards (see analysis): consumer(c) reads stage c&3 written at c-2, ordered by
    // the barrier after c-1 (c even) or c-2 (c odd). STS at c overwrites stage
    // (c+2)&3 = (c-2)&3, last read by compute(c-2), also pre-barrier. Both safe.
    for (int c = 0; c < NCHUNK; ++c) {
        const uint32_t tbc = sb + (c & 3) * STAGE_SZ;          // compute buffer
        const uint32_t tbs = sb + ((c + 2) & 3) * STAGE_SZ;    // staging buffer (chunk c+2)
        if (kh == 0) {
            if (c + 2 < NCHUNK) {
                STS_CHUNK(tbs);
                if (c + 3 < NCHUNK) { LDG_CHUNK(c + 3); }
            }
            COMPUTE_CHUNK(tbc);
        } else {
            COMPUTE_CHUNK(tbc);
            if (c + 2 < NCHUNK) {
                STS_CHUNK(tbs);
                if (c + 3 < NCHUNK) { LDG_CHUNK(c + 3); }
            }
        }
        if (c & 1) __syncthreads();   // barrier every 2 chunks (NCHUNK even -> last fires)
    }

    // ---- epilogue: zero Ls, merge kh pairs via 2-addend atomicAdd (deterministic) ----
    float* Ls = (float*)dsm;   // [128][65], overlays stage0
    for (int idx = tid; idx < BM * 65; idx += NT) Ls[idx] = 0.f;
    __syncthreads();
#pragma unroll
    for (int i = 0; i < 2; ++i) {
        int t0 = tg * 32 + i * 16 + l4;
#pragma unroll
        for (int j = 0; j < 4; ++j) {
            int e0 = eg * 32 + j * 8 + lk * 2;
            atomicAdd(&Ls[t0 * 65 + e0],           acc[i][j][0]);   // 2 commuting addends
            atomicAdd(&Ls[t0 * 65 + e0 + 1],       acc[i][j][1]);
            atomicAdd(&Ls[(t0 + 8) * 65 + e0],     acc[i][j][2]);
            atomicAdd(&Ls[(t0 + 8) * 65 + e0 + 1], acc[i][j][3]);
        }
    }
    __syncthreads();

    // per-token softmax / argmax (threads 0..127); store exp() back
    if (tid < BM) {
        float* lr = &Ls[tid * 65];
        float m = -1e30f; int am = 0;
#pragma unroll
        for (int e = 0; e < E_EXP; ++e) {
            float v = lr[e] + s_b[e];
            lr[e] = v;
            if (v > m) { m = v; am = e; }
        }
        float den = 0.f;
#pragma unroll
        for (int e = 0; e < E_EXP; ++e) {
            float p = expf(lr[e] - m);
            lr[e] = p;
            den += p;
        }
        float inv = 1.f / den;
        s_inv[tid] = inv;
        atomicAdd(&s_cnt[am], 1);          // int atomic: value-deterministic
        int gt = blk * BM + tid;
        out[gt]         = (float)am;       // pruned_idx (capacity 39322 > T: never pruned)
        out[T_TOK + gt] = inv;             // top1 score = exp(0)/den
    }
    __syncthreads();

    // per-expert score partial sums (fixed deterministic order; 8 slices of 16 tokens)
    {
        int e = tid & 63, h = tid >> 6;
        float s = 0.f;
#pragma unroll
        for (int i = 0; i < 16; ++i) {
            int t = h * 16 + i;
            s += Ls[t * 65 + e] * s_inv[t];
        }
        s_ps[tid] = s;
    }
    __syncthreads();
    if (tid < E_EXP) {
        float S = 0.f;
#pragma unroll
        for (int g = 0; g < 8; ++g) S += s_ps[g * 64 + tid];
        g_ssum[blk * E_EXP + tid] = S;
        g_cnt [blk * E_EXP + tid] = s_cnt[tid];
    }
    __syncthreads();

    // ---- fused loss: last block reduces (deterministic fixed-order) ----
    if (tid == 0) {
        __threadfence();
        int n = atomicAdd(&g_arrived, 1);
        s_last = (n == NBLK - 1) ? 1 : 0;
    }
    __syncthreads();
    if (s_last) {
        __threadfence();
        int e = tid & 63, h = tid >> 6;      // 8 groups of 16 blocks
        float ss = 0.f; int c = 0;
#pragma unroll
        for (int b = h * 16; b < h * 16 + 16; ++b) {
            ss += g_ssum[b * E_EXP + e];
            c  += g_cnt [b * E_EXP + e];
        }
        rs2[tid] = ss; rc2[tid] = c;
        __syncthreads();
        if (tid < E_EXP) {
            float S = 0.f; int C = 0;
#pragma unroll
            for (int g = 0; g < 8; ++g) { S += rs2[g * 64 + tid]; C += rc2[g * 64 + tid]; }
            rs2[tid] = S * (float)C;
        }
        __syncthreads();
        if (tid == 0) {
            float tot = 0.f;
#pragma unroll
            for (int e2 = 0; e2 < E_EXP; ++e2) tot += rs2[e2];
            out[2 * T_TOK] = tot * (float)E_EXP / ((float)T_TOK * (float)T_TOK);
            g_arrived = 0;   // reset for next graph replay
        }
    }
}

extern "C" void kernel_launch(void* const* d_in, const int* in_sizes, int n_in,
                              void* d_out, int out_size)
{
    const float* inp  = (const float*)d_in[0];
    const float* W    = (const float*)d_in[1];
    const float* bias = (const float*)d_in[2];
    float* out = (float*)d_out;   // [0,T) idx, [T,2T) top1 score, [2T] loss

    cudaFuncSetAttribute(gate_main, cudaFuncAttributeMaxDynamicSharedMemorySize, SMEM_BYTES);
    gate_main<<<NBLK, NT, SMEM_BYTES>>>(inp, W, bias, out);
}